// round 15
// baseline (speedup 1.0000x reference)
#include <cuda_runtime.h>
#include <cuda_fp16.h>
#include <math.h>

#define NN 100000
#define NE 1600000
#define IND 128
#define HID 64
#define GEMM1_BLOCKS ((NN + 127) / 128)          // 782
#define FILL_BLOCKS  ((NE + 255) / 256)          // 6250

// ---------------- scratch (device globals; never host-passed) ---------------
__device__ __half d_xw_h[(size_t)NN * HID];  // dinv-prescaled X@W rows, fp16
__device__ float  d_agg[(size_t)NN * HID];   // h buffer (fp32)
__device__ float  d_dinv[NN];
__device__ int    d_deg[NN];                 // zero at entry (cleanup invariant)
__device__ int    d_off[NN + 1];
__device__ int    d_cursor[NN];
__device__ int    d_csrc[NE];
__device__ float  d_g[HID];                  // zero at entry (cleanup invariant)

// PLANAR int32 layout (confirmed R6..R14): src = ei[0..E), dst = ei[E..2E)
__device__ __forceinline__ int edge_src(const int* ei, int e) {
    return (int)((unsigned)ei[e] % NN);
}
__device__ __forceinline__ int edge_dst(const int* ei, int e) {
    return (int)((unsigned)ei[NE + e] % NN);
}

// ---------------- (1) degree count (d_deg pre-zeroed by cleanup) ------------
__global__ void k_deg(const int* __restrict__ ei) {
    int e = blockIdx.x * blockDim.x + threadIdx.x;
    if (e < NE) atomicAdd(&d_deg[edge_dst(ei, e)], 1);
}

// ---------------- (2) scan + dinv (single block) -----------------------------
__global__ void k_scandinv() {
    __shared__ int part[1024];
    int t = threadIdx.x;
    for (int i = t; i < NN; i += 1024)
        d_dinv[i] = rsqrtf((float)d_deg[i] + 1.0f);
    const int CH = (NN + 1023) / 1024;
    int beg = t * CH, end = min(beg + CH, NN);
    int s = 0;
    for (int i = beg; i < end; i++) s += d_deg[i];
    part[t] = s;
    __syncthreads();
    for (int off = 1; off < 1024; off <<= 1) {
        int v = (t >= off) ? part[t - off] : 0;
        __syncthreads();
        part[t] += v;
        __syncthreads();
    }
    int run = (t == 0) ? 0 : part[t - 1];
    for (int i = beg; i < end; i++) {
        d_off[i] = run;
        d_cursor[i] = run;
        run += d_deg[i];
    }
    if (t == 1023) d_off[NN] = run;
}

// ---------------- GEMM tile body (register-tiled, R11 layout) ---------------
template <int K>
__device__ __forceinline__ void gemm_tile(const float* __restrict__ X,
                                          const float* __restrict__ W,
                                          float Ws[], float Xs[][33],
                                          int blk, int tid) {
    int ty = tid >> 3, tx = tid & 7;
    int base = blk * 128;

    for (int i = tid; i < K * HID / 4; i += 128)
        reinterpret_cast<float4*>(Ws)[i] = reinterpret_cast<const float4*>(W)[i];

    float acc[8][8];
#pragma unroll
    for (int m = 0; m < 8; m++)
#pragma unroll
        for (int n = 0; n < 8; n++) acc[m][n] = 0.0f;

    for (int kc = 0; kc < K; kc += 32) {
        __syncthreads();
#pragma unroll
        for (int p = 0; p < 8; p++) {
            int i = p * 128 + tid;
            int r = i >> 3;
            int c4 = i & 7;
            float4 v = make_float4(0.f, 0.f, 0.f, 0.f);
            if (base + r < NN)
                v = *reinterpret_cast<const float4*>(
                        &X[(size_t)(base + r) * K + kc + c4 * 4]);
            Xs[r][c4 * 4 + 0] = v.x;
            Xs[r][c4 * 4 + 1] = v.y;
            Xs[r][c4 * 4 + 2] = v.z;
            Xs[r][c4 * 4 + 3] = v.w;
        }
        __syncthreads();
#pragma unroll
        for (int c = 0; c < 32; c++) {
            float xv[8], wv[8];
#pragma unroll
            for (int m = 0; m < 8; m++) xv[m] = Xs[ty * 8 + m][c];
            const float4* wr = reinterpret_cast<const float4*>(&Ws[(kc + c) * HID + tx * 8]);
            float4 w0 = wr[0], w1 = wr[1];
            wv[0] = w0.x; wv[1] = w0.y; wv[2] = w0.z; wv[3] = w0.w;
            wv[4] = w1.x; wv[5] = w1.y; wv[6] = w1.z; wv[7] = w1.w;
#pragma unroll
            for (int m = 0; m < 8; m++)
#pragma unroll
                for (int n = 0; n < 8; n++) acc[m][n] += xv[m] * wv[n];
        }
    }

#pragma unroll
    for (int m = 0; m < 8; m++) {
        int node = base + ty * 8 + m;
        if (node >= NN) break;
        float sc = d_dinv[node];
        __half2 h[4];
#pragma unroll
        for (int n = 0; n < 4; n++)
            h[n] = __floats2half2_rn(acc[m][2 * n] * sc, acc[m][2 * n + 1] * sc);
        *reinterpret_cast<float4*>(d_xw_h + (size_t)node * HID + tx * 8) =
            *reinterpret_cast<const float4*>(h);
    }
}

// ---------------- (3) fused gemm1 + CSR fill --------------------------------
// blocks [0, GEMM1_BLOCKS): gemm tiles (128 thr used of 256)
// blocks [GEMM1_BLOCKS, +FILL_BLOCKS): CSR fill
__global__ __launch_bounds__(256) void k_gemm1_fill(const float* __restrict__ X,
                                                    const float* __restrict__ W,
                                                    const int* __restrict__ ei) {
    __shared__ float Ws[IND * HID];
    __shared__ float Xs[128][33];
    if (blockIdx.x < GEMM1_BLOCKS) {
        if (threadIdx.x < 128)
            gemm_tile<IND>(X, W, Ws, Xs, blockIdx.x, threadIdx.x);
        else {
            // participate in the tile's __syncthreads (8 k-chunks x 2 + none)
            for (int kc = 0; kc < IND; kc += 32) { __syncthreads(); __syncthreads(); }
        }
    } else {
        int e = (blockIdx.x - GEMM1_BLOCKS) * 256 + threadIdx.x;
        if (e < NE) {
            int s = edge_src(ei, e);
            int d = edge_dst(ei, e);
            int pos = atomicAdd(&d_cursor[d], 1);
            d_csrc[pos] = s;
        }
    }
}

// ---------------- (5) layer-2 GEMM ------------------------------------------
__global__ __launch_bounds__(128) void k_gemm2(const float* __restrict__ W) {
    __shared__ float Ws[HID * HID];
    __shared__ float Xs[128][33];
    gemm_tile<HID>(d_agg, W, Ws, Xs, blockIdx.x, threadIdx.x);
}

// ---------------- (4)/(6) gather: 8 lanes/node, fp16, float accumulation ----
__device__ __forceinline__ void acc8(float4 v, float* a) {
    const __half2* h = reinterpret_cast<const __half2*>(&v);
#pragma unroll
    for (int i = 0; i < 4; i++) {
        float2 f = __half22float2(h[i]);
        a[2 * i] += f.x;
        a[2 * i + 1] += f.y;
    }
}

__global__ void k_gather(const float* __restrict__ bias) {
    int node = blockIdx.x * (blockDim.x >> 3) + (threadIdx.x >> 3);
    int lane = threadIdx.x & 7;
    if (node >= NN) return;

    const __half* base = d_xw_h + (size_t)lane * 8;
    float a[8];
    {
        float4 sv = *reinterpret_cast<const float4*>(base + (size_t)node * HID);
        const __half2* h = reinterpret_cast<const __half2*>(&sv);
#pragma unroll
        for (int i = 0; i < 4; i++) {
            float2 f = __half22float2(h[i]);
            a[2 * i] = f.x;
            a[2 * i + 1] = f.y;
        }
    }

    int beg = d_off[node], end = d_off[node + 1];
    int k = beg;
    for (; k + 4 <= end; k += 4) {
        int s0 = d_csrc[k], s1 = d_csrc[k + 1], s2 = d_csrc[k + 2], s3 = d_csrc[k + 3];
        float4 v0 = *reinterpret_cast<const float4*>(base + (size_t)s0 * HID);
        float4 v1 = *reinterpret_cast<const float4*>(base + (size_t)s1 * HID);
        float4 v2 = *reinterpret_cast<const float4*>(base + (size_t)s2 * HID);
        float4 v3 = *reinterpret_cast<const float4*>(base + (size_t)s3 * HID);
        acc8(v0, a); acc8(v1, a); acc8(v2, a); acc8(v3, a);
    }
    for (; k < end; k++) {
        int s = d_csrc[k];
        float4 v = *reinterpret_cast<const float4*>(base + (size_t)s * HID);
        acc8(v, a);
    }

    float dd = d_dinv[node];
    const float* b = bias + lane * 8;
    float r[8];
#pragma unroll
    for (int i = 0; i < 8; i++) r[i] = fmaxf(a[i] * dd + b[i], 0.0f);

    float4* out = reinterpret_cast<float4*>(&d_agg[(size_t)node * HID + lane * 8]);
    out[0] = make_float4(r[0], r[1], r[2], r[3]);
    out[1] = make_float4(r[4], r[5], r[6], r[7]);
}

// ---------------- (7) column reduce ------------------------------------------
__global__ void k_reduce() {
    __shared__ float sh[256];
    int tid = threadIdx.x;
    size_t stride = (size_t)gridDim.x * blockDim.x;
    float bsum = 0.0f;
    for (size_t i = (size_t)blockIdx.x * blockDim.x + tid; i < (size_t)NN * HID; i += stride)
        bsum += d_agg[i];
    sh[tid] = bsum;
    __syncthreads();
    if (tid < HID) {
        float tot = sh[tid] + sh[tid + 64] + sh[tid + 128] + sh[tid + 192];
        atomicAdd(&d_g[tid], tot);
    }
}

// ---------------- (8) final ---------------------------------------------------
__global__ void k_final(const float* __restrict__ Wf, const float* __restrict__ bf,
                        float* __restrict__ out) {
    __shared__ float sh[HID];
    int j = threadIdx.x;
    sh[j] = d_g[j] * (1.0f / (float)NN) * Wf[j];
    __syncthreads();
    if (j < 32) sh[j] += sh[j + 32];
    __syncthreads();
    if (j == 0) {
        float s = 0.0f;
#pragma unroll
        for (int i = 0; i < 32; i++) s += sh[i];
        out[0] = 1.0f / (1.0f + expf(-(s + bf[0])));
    }
}

// ---------------- (9) cleanup: restore zero invariant ------------------------
__global__ void k_cleanup() {
    int i = blockIdx.x * blockDim.x + threadIdx.x;
    if (i < NN) d_deg[i] = 0;
    if (i < HID) d_g[i] = 0.0f;
}

extern "C" void kernel_launch(void* const* d_in, const int* in_sizes, int n_in,
                              void* d_out, int out_size) {
    const float* x   = (const float*)d_in[0];
    const int*   ei  = (const int*)d_in[1];
    const float* W1  = (const float*)d_in[2];
    const float* b1  = (const float*)d_in[3];
    const float* W2  = (const float*)d_in[4];
    const float* b2  = (const float*)d_in[5];
    const float* Wf  = (const float*)d_in[6];
    const float* bf  = (const float*)d_in[7];
    float* out = (float*)d_out;

    const int T = 256;
    int nblk_n = (NN + T - 1) / T;
    int nblk_e = (NE + T - 1) / T;
    int nblk_g = (NN * 8 + T - 1) / T;

    k_deg<<<nblk_e, T>>>(ei);                                  // 1
    k_scandinv<<<1, 1024>>>();                                 // 2
    k_gemm1_fill<<<GEMM1_BLOCKS + FILL_BLOCKS, 256>>>(x, W1, ei); // 3
    k_gather<<<nblk_g, T>>>(b1);                               // 4  <- profiled
    k_gemm2<<<GEMM1_BLOCKS, 128>>>(W2);                        // 5
    k_gather<<<nblk_g, T>>>(b2);                               // 6
    k_reduce<<<1024, T>>>();                                   // 7
    k_final<<<1, HID>>>(Wf, bf, out);                          // 8
    k_cleanup<<<nblk_n, T>>>();                                // 9
}

// round 16
// speedup vs baseline: 2.1946x; 2.1946x over previous
#include <cuda_runtime.h>
#include <cuda_fp16.h>
#include <math.h>

#define NN 100000
#define NE 1600000
#define IND 128
#define HID 64
#define SCAN_BLKS ((NN + 255) / 256)     // 391

// ---------------- scratch (device globals; never host-passed) ---------------
__device__ __half d_xw_h[(size_t)NN * HID];  // dinv-prescaled X@W rows, fp16
__device__ float  d_agg[(size_t)NN * HID];   // h buffer (fp32)
__device__ float  d_dinv[NN];
__device__ int    d_deg[NN];                 // zero at entry (cleanup invariant)
__device__ int    d_off[NN + 1];
__device__ int    d_cursor[NN];
__device__ int    d_csrc[NE];
__device__ int    d_bsum[SCAN_BLKS];
__device__ int    d_bbase[SCAN_BLKS];
__device__ float  d_g[HID];                  // zero at entry (cleanup invariant)

// PLANAR int32 layout (confirmed): src = ei[0..E), dst = ei[E..2E)
__device__ __forceinline__ int edge_src(const int* ei, int e) {
    return (int)((unsigned)ei[e] % NN);
}
__device__ __forceinline__ int edge_dst(const int* ei, int e) {
    return (int)((unsigned)ei[NE + e] % NN);
}

// ---------------- (1) degree count ------------------------------------------
__global__ void k_deg(const int* __restrict__ ei) {
    int e = blockIdx.x * blockDim.x + threadIdx.x;
    if (e < NE) atomicAdd(&d_deg[edge_dst(ei, e)], 1);
}

// ---------------- (2) scanA: dinv + block-local exclusive scan + block sum --
__global__ void k_scanA() {
    __shared__ int sh[256];
    int t = threadIdx.x;
    int i = blockIdx.x * 256 + t;
    int v = (i < NN) ? d_deg[i] : 0;
    if (i < NN) d_dinv[i] = rsqrtf((float)v + 1.0f);
    sh[t] = v;
    __syncthreads();
#pragma unroll
    for (int off = 1; off < 256; off <<= 1) {
        int u = (t >= off) ? sh[t - off] : 0;
        __syncthreads();
        sh[t] += u;
        __syncthreads();
    }
    if (i < NN) d_off[i] = sh[t] - v;               // local exclusive
    if (t == 255) d_bsum[blockIdx.x] = sh[255];     // block total
}

// ---------------- (3) scanB: exclusive scan of block sums (1 block) ---------
__global__ void k_scanB() {
    __shared__ int sh[512];
    int t = threadIdx.x;
    int v = (t < SCAN_BLKS) ? d_bsum[t] : 0;
    sh[t] = v;
    __syncthreads();
#pragma unroll
    for (int off = 1; off < 512; off <<= 1) {
        int u = (t >= off) ? sh[t - off] : 0;
        __syncthreads();
        sh[t] += u;
        __syncthreads();
    }
    if (t < SCAN_BLKS) d_bbase[t] = sh[t] - v;      // exclusive base
    if (t == 511) d_off[NN] = sh[511];              // total == NE
}

// ---------------- (4) scanC: globalize offsets + init cursors ---------------
__global__ void k_scanC() {
    int i = blockIdx.x * 256 + threadIdx.x;
    if (i < NN) {
        int o = d_off[i] + d_bbase[blockIdx.x];
        d_off[i] = o;
        d_cursor[i] = o;
    }
}

// ---------------- (5) CSR fill ------------------------------------------------
__global__ void k_fill(const int* __restrict__ ei) {
    int e = blockIdx.x * blockDim.x + threadIdx.x;
    if (e >= NE) return;
    int s = edge_src(ei, e);
    int d = edge_dst(ei, e);
    int pos = atomicAdd(&d_cursor[d], 1);
    d_csrc[pos] = s;
}

// ---------------- register-tiled GEMM: d_xw_h = fp16( dinv .* (X @ W) ) -----
template <int K, int LAYER>
__global__ __launch_bounds__(128) void k_gemm(const float* __restrict__ Xext,
                                              const float* __restrict__ W) {
    __shared__ float Ws[K * HID];
    __shared__ float Xs[128][33];
    const float* X = (LAYER == 1) ? Xext : d_agg;
    int tid = threadIdx.x;
    int ty = tid >> 3, tx = tid & 7;
    int base = blockIdx.x * 128;

    for (int i = tid; i < K * HID / 4; i += 128)
        reinterpret_cast<float4*>(Ws)[i] = reinterpret_cast<const float4*>(W)[i];

    float acc[8][8];
#pragma unroll
    for (int m = 0; m < 8; m++)
#pragma unroll
        for (int n = 0; n < 8; n++) acc[m][n] = 0.0f;

    for (int kc = 0; kc < K; kc += 32) {
        __syncthreads();
#pragma unroll
        for (int p = 0; p < 8; p++) {
            int i = p * 128 + tid;
            int r = i >> 3;
            int c4 = i & 7;
            float4 v = make_float4(0.f, 0.f, 0.f, 0.f);
            if (base + r < NN)
                v = *reinterpret_cast<const float4*>(
                        &X[(size_t)(base + r) * K + kc + c4 * 4]);
            Xs[r][c4 * 4 + 0] = v.x;
            Xs[r][c4 * 4 + 1] = v.y;
            Xs[r][c4 * 4 + 2] = v.z;
            Xs[r][c4 * 4 + 3] = v.w;
        }
        __syncthreads();
#pragma unroll
        for (int c = 0; c < 32; c++) {
            float xv[8], wv[8];
#pragma unroll
            for (int m = 0; m < 8; m++) xv[m] = Xs[ty * 8 + m][c];
            const float4* wr = reinterpret_cast<const float4*>(&Ws[(kc + c) * HID + tx * 8]);
            float4 w0 = wr[0], w1 = wr[1];
            wv[0] = w0.x; wv[1] = w0.y; wv[2] = w0.z; wv[3] = w0.w;
            wv[4] = w1.x; wv[5] = w1.y; wv[6] = w1.z; wv[7] = w1.w;
#pragma unroll
            for (int m = 0; m < 8; m++)
#pragma unroll
                for (int n = 0; n < 8; n++) acc[m][n] += xv[m] * wv[n];
        }
    }

#pragma unroll
    for (int m = 0; m < 8; m++) {
        int node = base + ty * 8 + m;
        if (node >= NN) break;
        float sc = d_dinv[node];
        __half2 h[4];
#pragma unroll
        for (int n = 0; n < 4; n++)
            h[n] = __floats2half2_rn(acc[m][2 * n] * sc, acc[m][2 * n + 1] * sc);
        *reinterpret_cast<float4*>(d_xw_h + (size_t)node * HID + tx * 8) =
            *reinterpret_cast<const float4*>(h);
    }
}

// ---------------- gather: 8 lanes/node, fp16, float accumulation ------------
__device__ __forceinline__ void acc8(float4 v, float* a) {
    const __half2* h = reinterpret_cast<const __half2*>(&v);
#pragma unroll
    for (int i = 0; i < 4; i++) {
        float2 f = __half22float2(h[i]);
        a[2 * i] += f.x;
        a[2 * i + 1] += f.y;
    }
}

__global__ void k_gather(const float* __restrict__ bias) {
    int node = blockIdx.x * (blockDim.x >> 3) + (threadIdx.x >> 3);
    int lane = threadIdx.x & 7;
    if (node >= NN) return;

    const __half* base = d_xw_h + (size_t)lane * 8;
    float a[8];
    {
        float4 sv = *reinterpret_cast<const float4*>(base + (size_t)node * HID);
        const __half2* h = reinterpret_cast<const __half2*>(&sv);
#pragma unroll
        for (int i = 0; i < 4; i++) {
            float2 f = __half22float2(h[i]);
            a[2 * i] = f.x;
            a[2 * i + 1] = f.y;
        }
    }

    int beg = d_off[node], end = d_off[node + 1];
    int k = beg;
    for (; k + 4 <= end; k += 4) {
        int s0 = d_csrc[k], s1 = d_csrc[k + 1], s2 = d_csrc[k + 2], s3 = d_csrc[k + 3];
        float4 v0 = *reinterpret_cast<const float4*>(base + (size_t)s0 * HID);
        float4 v1 = *reinterpret_cast<const float4*>(base + (size_t)s1 * HID);
        float4 v2 = *reinterpret_cast<const float4*>(base + (size_t)s2 * HID);
        float4 v3 = *reinterpret_cast<const float4*>(base + (size_t)s3 * HID);
        acc8(v0, a); acc8(v1, a); acc8(v2, a); acc8(v3, a);
    }
    for (; k < end; k++) {
        int s = d_csrc[k];
        float4 v = *reinterpret_cast<const float4*>(base + (size_t)s * HID);
        acc8(v, a);
    }

    float dd = d_dinv[node];
    const float* b = bias + lane * 8;
    float r[8];
#pragma unroll
    for (int i = 0; i < 8; i++) r[i] = fmaxf(a[i] * dd + b[i], 0.0f);

    float4* out = reinterpret_cast<float4*>(&d_agg[(size_t)node * HID + lane * 8]);
    out[0] = make_float4(r[0], r[1], r[2], r[3]);
    out[1] = make_float4(r[4], r[5], r[6], r[7]);
}

// ---------------- column reduce ------------------------------------------------
__global__ void k_reduce() {
    __shared__ float sh[256];
    int tid = threadIdx.x;
    size_t stride = (size_t)gridDim.x * blockDim.x;
    float bsum = 0.0f;
    for (size_t i = (size_t)blockIdx.x * blockDim.x + tid; i < (size_t)NN * HID; i += stride)
        bsum += d_agg[i];
    sh[tid] = bsum;
    __syncthreads();
    if (tid < HID) {
        float tot = sh[tid] + sh[tid + 64] + sh[tid + 128] + sh[tid + 192];
        atomicAdd(&d_g[tid], tot);
    }
}

// ---------------- final --------------------------------------------------------
__global__ void k_final(const float* __restrict__ Wf, const float* __restrict__ bf,
                        float* __restrict__ out) {
    __shared__ float sh[HID];
    int j = threadIdx.x;
    sh[j] = d_g[j] * (1.0f / (float)NN) * Wf[j];
    __syncthreads();
    if (j < 32) sh[j] += sh[j + 32];
    __syncthreads();
    if (j == 0) {
        float s = 0.0f;
#pragma unroll
        for (int i = 0; i < 32; i++) s += sh[i];
        out[0] = 1.0f / (1.0f + expf(-(s + bf[0])));
    }
}

// ---------------- cleanup: restore zero invariant ------------------------------
__global__ void k_cleanup() {
    int i = blockIdx.x * blockDim.x + threadIdx.x;
    if (i < NN) d_deg[i] = 0;
    if (i < HID) d_g[i] = 0.0f;
}

extern "C" void kernel_launch(void* const* d_in, const int* in_sizes, int n_in,
                              void* d_out, int out_size) {
    const float* x   = (const float*)d_in[0];
    const int*   ei  = (const int*)d_in[1];
    const float* W1  = (const float*)d_in[2];
    const float* b1  = (const float*)d_in[3];
    const float* W2  = (const float*)d_in[4];
    const float* b2  = (const float*)d_in[5];
    const float* Wf  = (const float*)d_in[6];
    const float* bf  = (const float*)d_in[7];
    float* out = (float*)d_out;

    const int T = 256;
    int nblk_n = (NN + T - 1) / T;       // 391
    int nblk_e = (NE + T - 1) / T;
    int nblk_g = (NN * 8 + T - 1) / T;

    k_deg<<<nblk_e, T>>>(ei);                            // 1
    k_scanA<<<SCAN_BLKS, 256>>>();                       // 2
    k_scanB<<<1, 512>>>();                               // 3
    k_scanC<<<SCAN_BLKS, 256>>>();                       // 4  <- profiled
    k_fill<<<nblk_e, T>>>(ei);                           // 5
    k_gemm<IND, 1><<<(NN + 127) / 128, 128>>>(x, W1);    // 6
    k_gather<<<nblk_g, T>>>(b1);                         // 7
    k_gemm<HID, 2><<<(NN + 127) / 128, 128>>>(nullptr, W2); // 8
    k_gather<<<nblk_g, T>>>(b2);                            // 9
    k_reduce<<<1024, T>>>();                             // 10
    k_final<<<1, HID>>>(Wf, bf, out);                    // 11
    k_cleanup<<<nblk_n, T>>>();                          // 12
}